// round 6
// baseline (speedup 1.0000x reference)
#include <cuda_runtime.h>
#include <cuda_bf16.h>
#include <cstdint>

// Problem dims (fixed by reference)
#define NB 8
#define NP 64
#define NS 512
#define ND 1024
#define NL 64
#define BPD (NB * NP)   // 512
#define BSD (NB * NS)   // 4096

// ---------------- device scratch (static globals; no allocs allowed) ----------------
__device__ float g_pred[BPD * ND];
__device__ float g_hid[BSD * ND];
__device__ float g_psc[BPD];
__device__ float g_asc[BSD];
__device__ float g_p2[BPD * NL];
__device__ float g_s2[BSD * NL];
__device__ __nv_bfloat16 g_pred_h[BPD * ND], g_pred_l[BPD * ND];
__device__ __nv_bfloat16 g_span_h[BSD * ND], g_span_l[BSD * ND];
__device__ __nv_bfloat16 g_wp_h[ND * ND], g_wp_l[ND * ND];
__device__ __nv_bfloat16 g_wa_h[ND * ND], g_wa_l[ND * ND];
__device__ __nv_bfloat16 g_w1t_h[(size_t)NL * ND * ND], g_w1t_l[(size_t)NL * ND * ND]; // [l][e][d]
__device__ __nv_bfloat16 g_u_h[(size_t)BPD * NL * ND],  g_u_l[(size_t)BPD * NL * ND];  // [bp][l][e]

// ---------------- small PTX helpers (all plain sm_80+ features) ----------------
__device__ __forceinline__ uint32_t smem_to_u32(const void* p) {
    uint32_t a;
    asm("{ .reg .u64 t; cvta.to.shared.u64 t, %1; cvt.u32.u64 %0, t; }" : "=r"(a) : "l"(p));
    return a;
}
__device__ __forceinline__ void ldm_x4(uint32_t* r, uint32_t a) {
    asm volatile("ldmatrix.sync.aligned.m8n8.x4.shared.b16 {%0,%1,%2,%3}, [%4];"
                 : "=r"(r[0]), "=r"(r[1]), "=r"(r[2]), "=r"(r[3]) : "r"(a));
}
__device__ __forceinline__ void mma_bf16(float* c, const uint32_t* a, const uint32_t* b) {
    asm volatile("mma.sync.aligned.m16n8k16.row.col.f32.bf16.bf16.f32 "
                 "{%0,%1,%2,%3}, {%4,%5,%6,%7}, {%8,%9}, {%0,%1,%2,%3};"
                 : "+f"(c[0]), "+f"(c[1]), "+f"(c[2]), "+f"(c[3])
                 : "r"(a[0]), "r"(a[1]), "r"(a[2]), "r"(a[3]), "r"(b[0]), "r"(b[1]));
}

// ---------------- tile loader: gmem (K-major, ld=ND) -> smem SW128 ----------------
// Tile = ROWS x 64 bf16, rows of 128 bytes, swizzle o ^= (o>>3)&0x70.
template <int ROWS>
__device__ __forceinline__ void load_tile(char* dst, const __nv_bfloat16* src, int tid) {
#pragma unroll
    for (int i = tid; i < ROWS * 8; i += 256) {
        int r = i >> 3, sg = i & 7;
        uint32_t o = (uint32_t)(r * 128 + sg * 16);
        uint32_t sw = o ^ ((o >> 3) & 0x70);
        *(uint4*)(dst + sw) = *(const uint4*)(src + (size_t)r * ND + sg * 8);
    }
}

// ---------------- core K-loop: 3 split segments x 16 chunks of K=64 ----------------
// A: 128 rows (M tile), B: BROWS rows (N tile). Warp tile = MF*16 x NF*8.
// Segments implement C = Ah*Bh + Ah*Bl + Al*Bh (bf16 hi/lo fp32 emulation).
template <int MF, int NF, int BROWS>
__device__ __forceinline__ void gemm_ks(
    float (&acc)[MF][NF][4],
    const __nv_bfloat16* Ah, const __nv_bfloat16* Al,
    const __nv_bfloat16* Bh, const __nv_bfloat16* Bl,
    char* sA, char* sB, uint32_t sAu, uint32_t sBu,
    int tid, int lane, int warpM, int warpN)
{
    const __nv_bfloat16* Aseg[3] = {Ah, Ah, Al};
    const __nv_bfloat16* Bseg[3] = {Bh, Bl, Bh};
#pragma unroll 1
    for (int seg = 0; seg < 3; seg++) {
        const __nv_bfloat16* Ab = Aseg[seg];
        const __nv_bfloat16* Bb = Bseg[seg];
#pragma unroll 1
        for (int ch = 0; ch < 16; ch++) {
            __syncthreads();
            load_tile<128>(sA, Ab + ch * 64, tid);
            load_tile<BROWS>(sB, Bb + ch * 64, tid);
            __syncthreads();
#pragma unroll
            for (int kk = 0; kk < 4; kk++) {
                uint32_t af[MF][4];
#pragma unroll
                for (int mf = 0; mf < MF; mf++) {
                    uint32_t row = warpM + mf * 16 + (lane & 15);
                    uint32_t kb = kk * 16 + ((lane >> 4) << 3);
                    uint32_t o = row * 128 + kb * 2;
                    o ^= ((o >> 3) & 0x70);
                    ldm_x4(af[mf], sAu + o);
                }
                uint32_t bf[NF][2];
#pragma unroll
                for (int nb = 0; nb < NF / 2; nb++) {
                    uint32_t row = warpN + nb * 16 + (lane & 7) + ((lane >> 4) & 1) * 8;
                    uint32_t kb = kk * 16 + ((lane >> 3) & 1) * 8;
                    uint32_t o = row * 128 + kb * 2;
                    o ^= ((o >> 3) & 0x70);
                    uint32_t t[4];
                    ldm_x4(t, sBu + o);
                    bf[2 * nb][0] = t[0]; bf[2 * nb][1] = t[1];
                    bf[2 * nb + 1][0] = t[2]; bf[2 * nb + 1][1] = t[3];
                }
#pragma unroll
                for (int mf = 0; mf < MF; mf++)
#pragma unroll
                    for (int nf = 0; nf < NF; nf++)
                        mma_bf16(acc[mf][nf], af[mf], bf[nf]);
            }
        }
    }
}

// ---------------- FFNN last layer: g_hid = relu(A @ W^T + bias) ----------------
// which==0: A=pred (M=512), W=Wp;  which==1: A=span (M=4096), W=Wa.
__global__ __launch_bounds__(256) void k_mma_ntrelu(int which, const float* __restrict__ bias)
{
    __shared__ __align__(128) char sA[16384];
    __shared__ __align__(128) char sB[16384];
    const uint32_t sAu = smem_to_u32(sA), sBu = smem_to_u32(sB);
    const int tid = threadIdx.x, lane = tid & 31, wid = tid >> 5;
    const int warpM = (wid >> 2) * 64, warpN = (wid & 3) * 32;
    const int nBase = blockIdx.x * 128, mBase = blockIdx.y * 128;

    const __nv_bfloat16* Ah = (which ? g_span_h : g_pred_h) + (size_t)mBase * ND;
    const __nv_bfloat16* Al = (which ? g_span_l : g_pred_l) + (size_t)mBase * ND;
    const __nv_bfloat16* Wh = (which ? g_wa_h : g_wp_h) + (size_t)nBase * ND;
    const __nv_bfloat16* Wl = (which ? g_wa_l : g_wp_l) + (size_t)nBase * ND;

    float acc[4][4][4] = {};
    gemm_ks<4, 4, 128>(acc, Ah, Al, Wh, Wl, sA, sB, sAu, sBu, tid, lane, warpM, warpN);

#pragma unroll
    for (int mf = 0; mf < 4; mf++)
#pragma unroll
        for (int h = 0; h < 2; h++) {
            int row = mBase + warpM + mf * 16 + (lane >> 2) + h * 8;
            float* orow = g_hid + (size_t)row * ND;
#pragma unroll
            for (int nf = 0; nf < 4; nf++) {
                int col = nBase + warpN + nf * 8 + (lane & 3) * 2;
                float2 v;
                v.x = fmaxf(acc[mf][nf][2 * h + 0] + bias[col], 0.f);
                v.y = fmaxf(acc[mf][nf][2 * h + 1] + bias[col + 1], 0.f);
                *(float2*)(orow + col) = v;
            }
        }
}

// ---------------- Stage 1: U[bp, l, e] = pred[bp,:] . W1t[l, e, :]; write bf16 hi/lo ----------------
__global__ __launch_bounds__(256) void k_u_mma()
{
    __shared__ __align__(128) char sA[16384];
    __shared__ __align__(128) char sB[16384];
    const uint32_t sAu = smem_to_u32(sA), sBu = smem_to_u32(sB);
    const int tid = threadIdx.x, lane = tid & 31, wid = tid >> 5;
    const int warpM = (wid >> 2) * 64, warpN = (wid & 3) * 32;
    const int nBase = blockIdx.x * 128, mBase = blockIdx.y * 128, l = blockIdx.z;

    const __nv_bfloat16* Ah = g_pred_h + (size_t)mBase * ND;
    const __nv_bfloat16* Al = g_pred_l + (size_t)mBase * ND;
    const __nv_bfloat16* Bh = g_w1t_h + ((size_t)l * ND + nBase) * ND;
    const __nv_bfloat16* Bl = g_w1t_l + ((size_t)l * ND + nBase) * ND;

    float acc[4][4][4] = {};
    gemm_ks<4, 4, 128>(acc, Ah, Al, Bh, Bl, sA, sB, sAu, sBu, tid, lane, warpM, warpN);

#pragma unroll
    for (int mf = 0; mf < 4; mf++)
#pragma unroll
        for (int h = 0; h < 2; h++) {
            int row = mBase + warpM + mf * 16 + (lane >> 2) + h * 8;
            size_t base = ((size_t)row * NL + l) * ND;
#pragma unroll
            for (int nf = 0; nf < 4; nf++) {
                int col = nBase + warpN + nf * 8 + (lane & 3) * 2;
                float v0 = acc[mf][nf][2 * h + 0], v1 = acc[mf][nf][2 * h + 1];
                __nv_bfloat16 h0 = __float2bfloat16(v0), h1 = __float2bfloat16(v1);
                __nv_bfloat16 q0 = __float2bfloat16(v0 - __bfloat162float(h0));
                __nv_bfloat16 q1 = __float2bfloat16(v1 - __bfloat162float(h1));
                *(__nv_bfloat162*)(g_u_h + base + col) = __halves2bfloat162(h0, h1);
                *(__nv_bfloat162*)(g_u_l + base + col) = __halves2bfloat162(q0, q1);
            }
        }
}

// ---------------- Stage 2 + full epilogue -> scores ----------------
// out[bp,s,l] = span[b,s,:] . U[bp,l,:] + p2 + s2 + bias + psc + asc; l==63 -> 0
__global__ __launch_bounds__(256) void k_final_mma(const float* __restrict__ bias,
                                                   float* __restrict__ out)
{
    __shared__ __align__(128) char sA[16384];
    __shared__ __align__(128) char sB[8192];
    const uint32_t sAu = smem_to_u32(sA), sBu = smem_to_u32(sB);
    const int tid = threadIdx.x, lane = tid & 31, wid = tid >> 5;
    const int warpM = (wid >> 1) * 32, warpN = (wid & 1) * 32;
    const int mBase = blockIdx.x * 128, bp = blockIdx.y, b = bp >> 6;

    const __nv_bfloat16* Ah = g_span_h + ((size_t)b * NS + mBase) * ND;
    const __nv_bfloat16* Al = g_span_l + ((size_t)b * NS + mBase) * ND;
    const __nv_bfloat16* Bh = g_u_h + (size_t)bp * NL * ND;
    const __nv_bfloat16* Bl = g_u_l + (size_t)bp * NL * ND;

    float acc[2][4][4] = {};
    gemm_ks<2, 4, 64>(acc, Ah, Al, Bh, Bl, sA, sB, sAu, sBu, tid, lane, warpM, warpN);

    const float* p2 = g_p2 + (size_t)bp * NL;
#pragma unroll
    for (int mf = 0; mf < 2; mf++)
#pragma unroll
        for (int h = 0; h < 2; h++) {
            int s = mBase + warpM + mf * 16 + (lane >> 2) + h * 8;
            size_t srow = (size_t)b * NS + s;
            float add = g_psc[bp] + g_asc[srow];
            const float* s2 = g_s2 + srow * NL;
            float* orow = out + ((size_t)bp * NS + s) * NL;
#pragma unroll
            for (int nf = 0; nf < 4; nf++) {
                int col = warpN + nf * 8 + (lane & 3) * 2;
                float2 v;
                v.x = acc[mf][nf][2 * h + 0] + p2[col] + s2[col] + bias[col] + add;
                v.y = acc[mf][nf][2 * h + 1] + p2[col + 1] + s2[col + 1] + bias[col + 1] + add;
                if (col + 1 == NL - 1) v.y = 0.f;   // null-label column
                *(float2*)(orow + col) = v;
            }
        }
}

// ---------------- gather predicate rows + bf16 split ----------------
__global__ __launch_bounds__(256) void k_gather_split(const float* __restrict__ span,
                                                      const int* __restrict__ preds) {
    int bp = blockIdx.x;
    int b = bp / NP;
    int s = preds[bp];
    float4 v = ((const float4*)(span + ((size_t)b * NS + s) * ND))[threadIdx.x];
    ((float4*)(g_pred + (size_t)bp * ND))[threadIdx.x] = v;
    __nv_bfloat16 h0 = __float2bfloat16(v.x), h1 = __float2bfloat16(v.y);
    __nv_bfloat16 h2 = __float2bfloat16(v.z), h3 = __float2bfloat16(v.w);
    __nv_bfloat162* ph = (__nv_bfloat162*)(g_pred_h + (size_t)bp * ND);
    __nv_bfloat162* pl = (__nv_bfloat162*)(g_pred_l + (size_t)bp * ND);
    ph[threadIdx.x * 2 + 0] = __halves2bfloat162(h0, h1);
    ph[threadIdx.x * 2 + 1] = __halves2bfloat162(h2, h3);
    pl[threadIdx.x * 2 + 0] = __halves2bfloat162(__float2bfloat16(v.x - __bfloat162float(h0)),
                                                 __float2bfloat16(v.y - __bfloat162float(h1)));
    pl[threadIdx.x * 2 + 1] = __halves2bfloat162(__float2bfloat16(v.z - __bfloat162float(h2)),
                                                 __float2bfloat16(v.w - __bfloat162float(h3)));
}

// ---------------- generic fp32 -> (hi, lo) bf16 split: 0->span, 1->Wp, 2->Wa ----------------
__global__ __launch_bounds__(256) void k_split4(const float* __restrict__ x, int which, int n4) {
    int i = blockIdx.x * 256 + threadIdx.x;
    if (i >= n4) return;
    __nv_bfloat16* H = which == 0 ? g_span_h : (which == 1 ? g_wp_h : g_wa_h);
    __nv_bfloat16* L = which == 0 ? g_span_l : (which == 1 ? g_wp_l : g_wa_l);
    float4 v = ((const float4*)x)[i];
    __nv_bfloat16 h0 = __float2bfloat16(v.x), h1 = __float2bfloat16(v.y);
    __nv_bfloat16 h2 = __float2bfloat16(v.z), h3 = __float2bfloat16(v.w);
    ((__nv_bfloat162*)H)[2 * i + 0] = __halves2bfloat162(h0, h1);
    ((__nv_bfloat162*)H)[2 * i + 1] = __halves2bfloat162(h2, h3);
    ((__nv_bfloat162*)L)[2 * i + 0] = __halves2bfloat162(__float2bfloat16(v.x - __bfloat162float(h0)),
                                                         __float2bfloat16(v.y - __bfloat162float(h1)));
    ((__nv_bfloat162*)L)[2 * i + 1] = __halves2bfloat162(__float2bfloat16(v.z - __bfloat162float(h2)),
                                                         __float2bfloat16(v.w - __bfloat162float(h3)));
}

// ---------------- W1 transpose + split: W1t[l][e][d] = split(W1[l][d][e]) ----------------
__global__ __launch_bounds__(256) void k_w1t(const float* __restrict__ W1) {
    __shared__ float t[32][33];
    const int l = blockIdx.z;
    const int e0 = blockIdx.x * 32, d0 = blockIdx.y * 32;
    const int tx = threadIdx.x, ty = threadIdx.y;   // (32, 8)
    const float* src = W1 + (size_t)l * ND * ND;
#pragma unroll
    for (int i = ty; i < 32; i += 8)
        t[i][tx] = src[(size_t)(d0 + i) * ND + e0 + tx];
    __syncthreads();
    const size_t dbase = (size_t)l * ND * ND;
#pragma unroll
    for (int i = ty; i < 32; i += 8) {
        float v = t[tx][i];                         // = W1[l][d0+tx][e0+i]
        __nv_bfloat16 h = __float2bfloat16(v);
        g_w1t_h[dbase + (size_t)(e0 + i) * ND + d0 + tx] = h;
        g_w1t_l[dbase + (size_t)(e0 + i) * ND + d0 + tx] =
            __float2bfloat16(v - __bfloat162float(h));
    }
}

// ---------------- row dot: score[r] = g_hid[r,:] . w  (0->psc, 1->asc) ----------------
__global__ __launch_bounds__(256) void k_rowdot(const float* __restrict__ w, int which) {
    int r = blockIdx.x;
    const float* Hp = g_hid + (size_t)r * ND;
    float s = 0.f;
    for (int j = threadIdx.x; j < ND; j += 256) s = fmaf(Hp[j], w[j], s);
    __shared__ float red[256];
    red[threadIdx.x] = s;
    __syncthreads();
    for (int o = 128; o > 0; o >>= 1) {
        if (threadIdx.x < o) red[threadIdx.x] += red[threadIdx.x + o];
        __syncthreads();
    }
    if (threadIdx.x == 0) (which ? g_asc : g_psc)[r] = red[0];
}

// ---------------- NN GEMM M x 64, K=1024 (p2 / s2), fp32 SIMT (small) ----------------
__global__ __launch_bounds__(256) void k_gemm_nn64(int useSpan, const float* __restrict__ span,
                                                   const float* __restrict__ Bw) {
    const float* A = useSpan ? span : g_pred;
    float* C = useSpan ? g_s2 : g_p2;
    __shared__ float As[16][64];
    __shared__ float Bs[16][64];
    const int tid = threadIdx.x;
    const int tx = tid & 15, ty = tid >> 4;
    const int rowBase = blockIdx.y * 64;
    const int alr = tid >> 2;
    const int alc = (tid & 3) << 2;
    const float* Ap = A + (size_t)(rowBase + alr) * ND + alc;
    const int blr = tid >> 4;
    const int blc = (tid & 15) << 2;
    const float* Bp = Bw + (size_t)blr * NL + blc;

    float acc[4][4];
#pragma unroll
    for (int i = 0; i < 4; i++)
#pragma unroll
        for (int j = 0; j < 4; j++) acc[i][j] = 0.f;

    for (int k0 = 0; k0 < ND; k0 += 16) {
        float4 av = *(const float4*)(Ap + k0);
        As[alc + 0][alr] = av.x;
        As[alc + 1][alr] = av.y;
        As[alc + 2][alr] = av.z;
        As[alc + 3][alr] = av.w;
        float4 bv = *(const float4*)(Bp + (size_t)k0 * NL);
        *(float4*)&Bs[blr][blc] = bv;
        __syncthreads();
#pragma unroll
        for (int k = 0; k < 16; k++) {
            float4 a4 = *(const float4*)&As[k][ty * 4];
            float4 b4 = *(const float4*)&Bs[k][tx * 4];
            float a[4] = {a4.x, a4.y, a4.z, a4.w};
            float bb[4] = {b4.x, b4.y, b4.z, b4.w};
#pragma unroll
            for (int i = 0; i < 4; i++)
#pragma unroll
                for (int j = 0; j < 4; j++)
                    acc[i][j] = fmaf(a[i], bb[j], acc[i][j]);
        }
        __syncthreads();
    }
#pragma unroll
    for (int i = 0; i < 4; i++) {
        int row = rowBase + ty * 4 + i;
        *(float4*)(C + (size_t)row * NL + tx * 4) =
            make_float4(acc[i][0], acc[i][1], acc[i][2], acc[i][3]);
    }
}

// ---------------- labels cast + tail zero ----------------
__global__ void k_labels(const int* __restrict__ lab, float* __restrict__ out, int n) {
    int i = blockIdx.x * blockDim.x + threadIdx.x;
    if (i < n) out[i] = (float)lab[i];
}
__global__ void k_zero(float* __restrict__ out, int n) {
    int i = blockIdx.x * blockDim.x + threadIdx.x;
    if (i < n) out[i] = 0.f;
}

// ---------------- host ----------------
extern "C" void kernel_launch(void* const* d_in, const int* in_sizes, int n_in,
                              void* d_out, int out_size)
{
    const float* span   = (const float*)d_in[0];
    const int*   preds  = (const int*)d_in[1];
    const int*   labels = (const int*)d_in[2];
    // d_in[3] = len_info (dense, unused)
    // FFNN bug: only the LAST layer (index 1) of each stack matters.
    const float* Wp   = (const float*)d_in[4] + (size_t)ND * ND;
    const float* bpv  = (const float*)d_in[5] + ND;
    const float* Wa   = (const float*)d_in[6] + (size_t)ND * ND;
    const float* bav  = (const float*)d_in[7] + ND;
    const float* wp   = (const float*)d_in[8];
    const float* wa   = (const float*)d_in[9];
    const float* W1   = (const float*)d_in[10];
    const float* W2   = (const float*)d_in[11];
    const float* bias = (const float*)d_in[12];
    float* out = (float*)d_out;

    // 1) gather + splits + W1 transpose-split
    k_gather_split<<<BPD, 256>>>(span, preds);
    k_split4<<<(BSD * ND / 4 + 255) / 256, 256>>>(span, 0, BSD * ND / 4);
    k_split4<<<(ND * ND / 4 + 255) / 256, 256>>>(Wp, 1, ND * ND / 4);
    k_split4<<<(ND * ND / 4 + 255) / 256, 256>>>(Wa, 2, ND * ND / 4);
    k_w1t<<<dim3(32, 32, 64), dim3(32, 8)>>>(W1);

    // 2) unary scores (HMMA FFNN last layer + rowdot)
    k_mma_ntrelu<<<dim3(8, 4), 256>>>(0, bpv);
    k_rowdot<<<BPD, 256>>>(wp, 0);
    k_mma_ntrelu<<<dim3(8, 32), 256>>>(1, bav);
    k_rowdot<<<BSD, 256>>>(wa, 1);

    // 3) concat-linear terms
    k_gemm_nn64<<<dim3(1, BPD / 64), 256>>>(0, span, W2);
    k_gemm_nn64<<<dim3(1, BSD / 64), 256>>>(1, span, W2 + (size_t)ND * NL);

    // 4) bilinear stage 1 (HMMA, bf16 split, U -> bf16 hi/lo)
    k_u_mma<<<dim3(8, 4, 64), 256>>>();

    // 5) bilinear stage 2 + full epilogue (HMMA)
    k_final_mma<<<dim3(4, 512), 256>>>(bias, out);

    // 6) labels + tail
    const int n_scores = NB * NP * NS * NL;
    const int n_lab = NB * NP * NS;
    int written = n_scores;
    if (out_size >= n_scores + n_lab) {
        k_labels<<<(n_lab + 255) / 256, 256>>>(labels, out + n_scores, n_lab);
        written += n_lab;
    }
    if (out_size > written) {
        int rem = out_size - written;
        k_zero<<<(rem + 255) / 256, 256>>>(out + written, rem);
    }
}

// round 7
// speedup vs baseline: 3.3039x; 3.3039x over previous
#include <cuda_runtime.h>
#include <cuda_bf16.h>
#include <cstdint>

// Problem dims (fixed by reference)
#define NB 8
#define NP 64
#define NS 512
#define ND 1024
#define NL 64
#define BPD (NB * NP)   // 512
#define BSD (NB * NS)   // 4096

// ---------------- device scratch (static globals; no allocs allowed) ----------------
__device__ float g_pred[BPD * ND];
__device__ float g_hid[BSD * ND];
__device__ float g_psc[BPD];
__device__ float g_asc[BSD];
__device__ float g_p2[BPD * NL];
__device__ float g_s2[BSD * NL];
__device__ __nv_bfloat16 g_pred_h[BPD * ND], g_pred_l[BPD * ND];
__device__ __nv_bfloat16 g_span_h[BSD * ND], g_span_l[BSD * ND];
__device__ __nv_bfloat16 g_wp_h[ND * ND], g_wp_l[ND * ND];
__device__ __nv_bfloat16 g_wa_h[ND * ND], g_wa_l[ND * ND];
__device__ __nv_bfloat16 g_w1t_h[(size_t)NL * ND * ND], g_w1t_l[(size_t)NL * ND * ND]; // [l][e][d]
__device__ __nv_bfloat16 g_u_h[(size_t)BPD * NL * ND],  g_u_l[(size_t)BPD * NL * ND];  // [bp][l][e]

// ---------------- PTX helpers (plain sm_80+ features only) ----------------
__device__ __forceinline__ uint32_t smem_to_u32(const void* p) {
    uint32_t a;
    asm("{ .reg .u64 t; cvta.to.shared.u64 t, %1; cvt.u32.u64 %0, t; }" : "=r"(a) : "l"(p));
    return a;
}
__device__ __forceinline__ void ldm_x4(uint32_t* r, uint32_t a) {
    asm volatile("ldmatrix.sync.aligned.m8n8.x4.shared.b16 {%0,%1,%2,%3}, [%4];"
                 : "=r"(r[0]), "=r"(r[1]), "=r"(r[2]), "=r"(r[3]) : "r"(a));
}
__device__ __forceinline__ void mma_bf16(float* c, const uint32_t* a, const uint32_t* b) {
    asm volatile("mma.sync.aligned.m16n8k16.row.col.f32.bf16.bf16.f32 "
                 "{%0,%1,%2,%3}, {%4,%5,%6,%7}, {%8,%9}, {%0,%1,%2,%3};"
                 : "+f"(c[0]), "+f"(c[1]), "+f"(c[2]), "+f"(c[3])
                 : "r"(a[0]), "r"(a[1]), "r"(a[2]), "r"(a[3]), "r"(b[0]), "r"(b[1]));
}
__device__ __forceinline__ void cp16(uint32_t d, const void* s) {
    asm volatile("cp.async.cg.shared.global [%0], [%1], 16;" :: "r"(d), "l"(s));
}
#define CP_COMMIT() asm volatile("cp.async.commit_group;" ::: "memory")
#define CP_WAIT1()  asm volatile("cp.async.wait_group 1;" ::: "memory")
#define CP_WAIT0()  asm volatile("cp.async.wait_group 0;" ::: "memory")

// Stage layout (bytes from stage base): Ah @0 (16KB), Al @16K, Bh @32K, Bl @32K+BROWS*128
// Each tile row = 64 bf16 = 128B, SW128 swizzle o ^= (o>>3)&0x70.
template <int BROWS>
__device__ __forceinline__ void prefetch_chunk(
    uint32_t st, const __nv_bfloat16* Ah, const __nv_bfloat16* Al,
    const __nv_bfloat16* Bh, const __nv_bfloat16* Bl, int ch, int tid)
{
    const int co = ch * 64;
#pragma unroll
    for (int i = tid; i < 1024; i += 256) {
        int r = i >> 3, sg = i & 7;
        uint32_t o = (uint32_t)(r * 128 + sg * 16);
        o ^= (o >> 3) & 0x70;
        const size_t goff = (size_t)r * ND + co + sg * 8;
        cp16(st + o, Ah + goff);
        cp16(st + 16384 + o, Al + goff);
    }
#pragma unroll
    for (int i = tid; i < BROWS * 8; i += 256) {
        int r = i >> 3, sg = i & 7;
        uint32_t o = (uint32_t)(r * 128 + sg * 16);
        o ^= (o >> 3) & 0x70;
        const size_t goff = (size_t)r * ND + co + sg * 8;
        cp16(st + 32768 + o, Bh + goff);
        cp16(st + 32768 + BROWS * 128 + o, Bl + goff);
    }
}

// Per-chunk MMA: fragments loaded ONCE per kk, reused by the 3 split products
// C += Ah*Bh + Ah*Bl + Al*Bh
template <int MF, int NF, int BROWS>
__device__ __forceinline__ void mma_chunk(float (&acc)[MF][NF][4], uint32_t st,
                                          int lane, int warpM, int warpN)
{
#pragma unroll
    for (int kk = 0; kk < 4; kk++) {
        uint32_t afH[MF][4], afL[MF][4];
#pragma unroll
        for (int mf = 0; mf < MF; mf++) {
            uint32_t row = warpM + mf * 16 + (lane & 15);
            uint32_t kb = kk * 16 + ((lane >> 4) << 3);
            uint32_t o = row * 128 + kb * 2;
            o ^= (o >> 3) & 0x70;
            ldm_x4(afH[mf], st + o);
            ldm_x4(afL[mf], st + 16384 + o);
        }
        uint32_t bfH[NF][2], bfL[NF][2];
#pragma unroll
        for (int nb = 0; nb < NF / 2; nb++) {
            uint32_t row = warpN + nb * 16 + (lane & 7) + ((lane >> 4) & 1) * 8;
            uint32_t kb = kk * 16 + ((lane >> 3) & 1) * 8;
            uint32_t o = row * 128 + kb * 2;
            o ^= (o >> 3) & 0x70;
            uint32_t t[4];
            ldm_x4(t, st + 32768 + o);
            bfH[2 * nb][0] = t[0]; bfH[2 * nb][1] = t[1];
            bfH[2 * nb + 1][0] = t[2]; bfH[2 * nb + 1][1] = t[3];
            ldm_x4(t, st + 32768 + BROWS * 128 + o);
            bfL[2 * nb][0] = t[0]; bfL[2 * nb][1] = t[1];
            bfL[2 * nb + 1][0] = t[2]; bfL[2 * nb + 1][1] = t[3];
        }
#pragma unroll
        for (int mf = 0; mf < MF; mf++)
#pragma unroll
            for (int nf = 0; nf < NF; nf++) {
                mma_bf16(acc[mf][nf], afH[mf], bfH[nf]);
                mma_bf16(acc[mf][nf], afH[mf], bfL[nf]);
                mma_bf16(acc[mf][nf], afL[mf], bfH[nf]);
            }
    }
}

// Double-buffered pipeline over 16 K-chunks of 64
template <int MF, int NF, int BROWS>
__device__ __forceinline__ void gemm_pipe(
    float (&acc)[MF][NF][4],
    const __nv_bfloat16* Ah, const __nv_bfloat16* Al,
    const __nv_bfloat16* Bh, const __nv_bfloat16* Bl,
    uint32_t sm, int tid, int lane, int warpM, int warpN)
{
    const uint32_t STAGE = 32768u + 2u * BROWS * 128u;
    prefetch_chunk<BROWS>(sm, Ah, Al, Bh, Bl, 0, tid);
    CP_COMMIT();
#pragma unroll 1
    for (int ch = 0; ch < 16; ch++) {
        uint32_t st = sm + (uint32_t)(ch & 1) * STAGE;
        if (ch + 1 < 16) {
            prefetch_chunk<BROWS>(sm + (uint32_t)((ch + 1) & 1) * STAGE, Ah, Al, Bh, Bl, ch + 1, tid);
            CP_COMMIT();
            CP_WAIT1();
        } else {
            CP_WAIT0();
        }
        __syncthreads();
        mma_chunk<MF, NF, BROWS>(acc, st, lane, warpM, warpN);
        __syncthreads();
    }
}

// ---------------- FFNN last layer: g_hid = relu(A @ W^T + bias) ----------------
__global__ __launch_bounds__(256, 1) void k_mma_ntrelu(int which, const float* __restrict__ bias)
{
    extern __shared__ __align__(1024) char dsm[];
    const uint32_t sm = smem_to_u32(dsm);
    const int tid = threadIdx.x, lane = tid & 31, wid = tid >> 5;
    const int warpM = (wid >> 2) * 64, warpN = (wid & 3) * 32;
    const int nBase = blockIdx.x * 128, mBase = blockIdx.y * 128;

    const __nv_bfloat16* Ah = (which ? g_span_h : g_pred_h) + (size_t)mBase * ND;
    const __nv_bfloat16* Al = (which ? g_span_l : g_pred_l) + (size_t)mBase * ND;
    const __nv_bfloat16* Wh = (which ? g_wa_h : g_wp_h) + (size_t)nBase * ND;
    const __nv_bfloat16* Wl = (which ? g_wa_l : g_wp_l) + (size_t)nBase * ND;

    float acc[4][4][4] = {};
    gemm_pipe<4, 4, 128>(acc, Ah, Al, Wh, Wl, sm, tid, lane, warpM, warpN);

#pragma unroll
    for (int mf = 0; mf < 4; mf++)
#pragma unroll
        for (int h = 0; h < 2; h++) {
            int row = mBase + warpM + mf * 16 + (lane >> 2) + h * 8;
            float* orow = g_hid + (size_t)row * ND;
#pragma unroll
            for (int nf = 0; nf < 4; nf++) {
                int col = nBase + warpN + nf * 8 + (lane & 3) * 2;
                float2 v;
                v.x = fmaxf(acc[mf][nf][2 * h + 0] + bias[col], 0.f);
                v.y = fmaxf(acc[mf][nf][2 * h + 1] + bias[col + 1], 0.f);
                *(float2*)(orow + col) = v;
            }
        }
}

// ---------------- Stage 1: U[bp, l, e] = pred[bp,:] . W1t[l, e, :]; write bf16 hi/lo ----------------
__global__ __launch_bounds__(256, 1) void k_u_mma()
{
    extern __shared__ __align__(1024) char dsm[];
    const uint32_t sm = smem_to_u32(dsm);
    const int tid = threadIdx.x, lane = tid & 31, wid = tid >> 5;
    const int warpM = (wid >> 2) * 64, warpN = (wid & 3) * 32;
    const int nBase = blockIdx.x * 128, mBase = blockIdx.y * 128, l = blockIdx.z;

    const __nv_bfloat16* Ah = g_pred_h + (size_t)mBase * ND;
    const __nv_bfloat16* Al = g_pred_l + (size_t)mBase * ND;
    const __nv_bfloat16* Bh = g_w1t_h + ((size_t)l * ND + nBase) * ND;
    const __nv_bfloat16* Bl = g_w1t_l + ((size_t)l * ND + nBase) * ND;

    float acc[4][4][4] = {};
    gemm_pipe<4, 4, 128>(acc, Ah, Al, Bh, Bl, sm, tid, lane, warpM, warpN);

#pragma unroll
    for (int mf = 0; mf < 4; mf++)
#pragma unroll
        for (int h = 0; h < 2; h++) {
            int row = mBase + warpM + mf * 16 + (lane >> 2) + h * 8;
            size_t base = ((size_t)row * NL + l) * ND;
#pragma unroll
            for (int nf = 0; nf < 4; nf++) {
                int col = nBase + warpN + nf * 8 + (lane & 3) * 2;
                float v0 = acc[mf][nf][2 * h + 0], v1 = acc[mf][nf][2 * h + 1];
                __nv_bfloat16 h0 = __float2bfloat16(v0), h1 = __float2bfloat16(v1);
                __nv_bfloat16 q0 = __float2bfloat16(v0 - __bfloat162float(h0));
                __nv_bfloat16 q1 = __float2bfloat16(v1 - __bfloat162float(h1));
                *(__nv_bfloat162*)(g_u_h + base + col) = __halves2bfloat162(h0, h1);
                *(__nv_bfloat162*)(g_u_l + base + col) = __halves2bfloat162(q0, q1);
            }
        }
}

// ---------------- Stage 2 + full epilogue -> scores ----------------
__global__ __launch_bounds__(256, 2) void k_final_mma(const float* __restrict__ bias,
                                                      float* __restrict__ out)
{
    extern __shared__ __align__(1024) char dsm[];
    const uint32_t sm = smem_to_u32(dsm);
    const int tid = threadIdx.x, lane = tid & 31, wid = tid >> 5;
    const int warpM = (wid >> 1) * 32, warpN = (wid & 1) * 32;
    const int mBase = blockIdx.x * 128, bp = blockIdx.y, b = bp >> 6;

    const __nv_bfloat16* Ah = g_span_h + ((size_t)b * NS + mBase) * ND;
    const __nv_bfloat16* Al = g_span_l + ((size_t)b * NS + mBase) * ND;
    const __nv_bfloat16* Bh = g_u_h + (size_t)bp * NL * ND;
    const __nv_bfloat16* Bl = g_u_l + (size_t)bp * NL * ND;

    float acc[2][4][4] = {};
    gemm_pipe<2, 4, 64>(acc, Ah, Al, Bh, Bl, sm, tid, lane, warpM, warpN);

    const float* p2 = g_p2 + (size_t)bp * NL;
#pragma unroll
    for (int mf = 0; mf < 2; mf++)
#pragma unroll
        for (int h = 0; h < 2; h++) {
            int s = mBase + warpM + mf * 16 + (lane >> 2) + h * 8;
            size_t srow = (size_t)b * NS + s;
            float add = g_psc[bp] + g_asc[srow];
            const float* s2 = g_s2 + srow * NL;
            float* orow = out + ((size_t)bp * NS + s) * NL;
#pragma unroll
            for (int nf = 0; nf < 4; nf++) {
                int col = warpN + nf * 8 + (lane & 3) * 2;
                float2 v;
                v.x = acc[mf][nf][2 * h + 0] + p2[col] + s2[col] + bias[col] + add;
                v.y = acc[mf][nf][2 * h + 1] + p2[col + 1] + s2[col + 1] + bias[col + 1] + add;
                if (col + 1 == NL - 1) v.y = 0.f;   // null-label column
                *(float2*)(orow + col) = v;
            }
        }
}

// ---------------- gather predicate rows + bf16 split ----------------
__global__ __launch_bounds__(256) void k_gather_split(const float* __restrict__ span,
                                                      const int* __restrict__ preds) {
    int bp = blockIdx.x;
    int b = bp / NP;
    int s = preds[bp];
    float4 v = ((const float4*)(span + ((size_t)b * NS + s) * ND))[threadIdx.x];
    ((float4*)(g_pred + (size_t)bp * ND))[threadIdx.x] = v;
    __nv_bfloat16 h0 = __float2bfloat16(v.x), h1 = __float2bfloat16(v.y);
    __nv_bfloat16 h2 = __float2bfloat16(v.z), h3 = __float2bfloat16(v.w);
    __nv_bfloat162* ph = (__nv_bfloat162*)(g_pred_h + (size_t)bp * ND);
    __nv_bfloat162* pl = (__nv_bfloat162*)(g_pred_l + (size_t)bp * ND);
    ph[threadIdx.x * 2 + 0] = __halves2bfloat162(h0, h1);
    ph[threadIdx.x * 2 + 1] = __halves2bfloat162(h2, h3);
    pl[threadIdx.x * 2 + 0] = __halves2bfloat162(__float2bfloat16(v.x - __bfloat162float(h0)),
                                                 __float2bfloat16(v.y - __bfloat162float(h1)));
    pl[threadIdx.x * 2 + 1] = __halves2bfloat162(__float2bfloat16(v.z - __bfloat162float(h2)),
                                                 __float2bfloat16(v.w - __bfloat162float(h3)));
}

// ---------------- generic fp32 -> (hi, lo) bf16 split: 0->span, 1->Wp, 2->Wa ----------------
__global__ __launch_bounds__(256) void k_split4(const float* __restrict__ x, int which, int n4) {
    int i = blockIdx.x * 256 + threadIdx.x;
    if (i >= n4) return;
    __nv_bfloat16* H = which == 0 ? g_span_h : (which == 1 ? g_wp_h : g_wa_h);
    __nv_bfloat16* L = which == 0 ? g_span_l : (which == 1 ? g_wp_l : g_wa_l);
    float4 v = ((const float4*)x)[i];
    __nv_bfloat16 h0 = __float2bfloat16(v.x), h1 = __float2bfloat16(v.y);
    __nv_bfloat16 h2 = __float2bfloat16(v.z), h3 = __float2bfloat16(v.w);
    ((__nv_bfloat162*)H)[2 * i + 0] = __halves2bfloat162(h0, h1);
    ((__nv_bfloat162*)H)[2 * i + 1] = __halves2bfloat162(h2, h3);
    ((__nv_bfloat162*)L)[2 * i + 0] = __halves2bfloat162(__float2bfloat16(v.x - __bfloat162float(h0)),
                                                         __float2bfloat16(v.y - __bfloat162float(h1)));
    ((__nv_bfloat162*)L)[2 * i + 1] = __halves2bfloat162(__float2bfloat16(v.z - __bfloat162float(h2)),
                                                         __float2bfloat16(v.w - __bfloat162float(h3)));
}

// ---------------- W1 transpose + split: W1t[l][e][d] = split(W1[l][d][e]) ----------------
__global__ __launch_bounds__(256) void k_w1t(const float* __restrict__ W1) {
    __shared__ float t[32][33];
    const int l = blockIdx.z;
    const int e0 = blockIdx.x * 32, d0 = blockIdx.y * 32;
    const int tx = threadIdx.x, ty = threadIdx.y;   // (32, 8)
    const float* src = W1 + (size_t)l * ND * ND;
#pragma unroll
    for (int i = ty; i < 32; i += 8)
        t[i][tx] = src[(size_t)(d0 + i) * ND + e0 + tx];
    __syncthreads();
    const size_t dbase = (size_t)l * ND * ND;
#pragma unroll
    for (int i = ty; i < 32; i += 8) {
        float v = t[tx][i];                         // = W1[l][d0+tx][e0+i]
        __nv_bfloat16 h = __float2bfloat16(v);
        g_w1t_h[dbase + (size_t)(e0 + i) * ND + d0 + tx] = h;
        g_w1t_l[dbase + (size_t)(e0 + i) * ND + d0 + tx] =
            __float2bfloat16(v - __bfloat162float(h));
    }
}

// ---------------- row dot: score[r] = g_hid[r,:] . w  (0->psc, 1->asc) ----------------
__global__ __launch_bounds__(256) void k_rowdot(const float* __restrict__ w, int which) {
    int r = blockIdx.x;
    const float* Hp = g_hid + (size_t)r * ND;
    float s = 0.f;
    for (int j = threadIdx.x; j < ND; j += 256) s = fmaf(Hp[j], w[j], s);
    __shared__ float red[256];
    red[threadIdx.x] = s;
    __syncthreads();
    for (int o = 128; o > 0; o >>= 1) {
        if (threadIdx.x < o) red[threadIdx.x] += red[threadIdx.x + o];
        __syncthreads();
    }
    if (threadIdx.x == 0) (which ? g_asc : g_psc)[r] = red[0];
}

// ---------------- NN GEMM M x 64, K=1024 (p2 / s2), fp32 SIMT (small) ----------------
__global__ __launch_bounds__(256) void k_gemm_nn64(int useSpan, const float* __restrict__ span,
                                                   const float* __restrict__ Bw) {
    const float* A = useSpan ? span : g_pred;
    float* C = useSpan ? g_s2 : g_p2;
    __shared__ float As[16][64];
    __shared__ float Bs[16][64];
    const int tid = threadIdx.x;
    const int tx = tid & 15, ty = tid >> 4;
    const int rowBase = blockIdx.y * 64;
    const int alr = tid >> 2;
    const int alc = (tid & 3) << 2;
    const float* Ap = A + (size_t)(rowBase + alr) * ND + alc;
    const int blr = tid >> 4;
    const int blc = (tid & 15) << 2;
    const float* Bp = Bw + (size_t)blr * NL + blc;

    float acc[4][4];
#pragma unroll
    for (int i = 0; i < 4; i++)
#pragma unroll
        for (int j = 0; j < 4; j++) acc[i][j] = 0.f;

    for (int k0 = 0; k0 < ND; k0 += 16) {
        float4 av = *(const float4*)(Ap + k0);
        As[alc + 0][alr] = av.x;
        As[alc + 1][alr] = av.y;
        As[alc + 2][alr] = av.z;
        As[alc + 3][alr] = av.w;
        float4 bv = *(const float4*)(Bp + (size_t)k0 * NL);
        *(float4*)&Bs[blr][blc] = bv;
        __syncthreads();
#pragma unroll
        for (int k = 0; k < 16; k++) {
            float4 a4 = *(const float4*)&As[k][ty * 4];
            float4 b4 = *(const float4*)&Bs[k][tx * 4];
            float a[4] = {a4.x, a4.y, a4.z, a4.w};
            float bb[4] = {b4.x, b4.y, b4.z, b4.w};
#pragma unroll
            for (int i = 0; i < 4; i++)
#pragma unroll
                for (int j = 0; j < 4; j++)
                    acc[i][j] = fmaf(a[i], bb[j], acc[i][j]);
        }
        __syncthreads();
    }
#pragma unroll
    for (int i = 0; i < 4; i++) {
        int row = rowBase + ty * 4 + i;
        *(float4*)(C + (size_t)row * NL + tx * 4) =
            make_float4(acc[i][0], acc[i][1], acc[i][2], acc[i][3]);
    }
}

// ---------------- labels cast + tail zero ----------------
__global__ void k_labels(const int* __restrict__ lab, float* __restrict__ out, int n) {
    int i = blockIdx.x * blockDim.x + threadIdx.x;
    if (i < n) out[i] = (float)lab[i];
}
__global__ void k_zero(float* __restrict__ out, int n) {
    int i = blockIdx.x * blockDim.x + threadIdx.x;
    if (i < n) out[i] = 0.f;
}

// ---------------- host ----------------
extern "C" void kernel_launch(void* const* d_in, const int* in_sizes, int n_in,
                              void* d_out, int out_size)
{
    const float* span   = (const float*)d_in[0];
    const int*   preds  = (const int*)d_in[1];
    const int*   labels = (const int*)d_in[2];
    // d_in[3] = len_info (dense, unused)
    // FFNN bug: only the LAST layer (index 1) of each stack matters.
    const float* Wp   = (const float*)d_in[4] + (size_t)ND * ND;
    const float* bpv  = (const float*)d_in[5] + ND;
    const float* Wa   = (const float*)d_in[6] + (size_t)ND * ND;
    const float* bav  = (const float*)d_in[7] + ND;
    const float* wp   = (const float*)d_in[8];
    const float* wa   = (const float*)d_in[9];
    const float* W1   = (const float*)d_in[10];
    const float* W2   = (const float*)d_in[11];
    const float* bias = (const float*)d_in[12];
    float* out = (float*)d_out;

    // dynamic smem: big kernels 2 stages x (16K+16K+16K+16K) = 128KB; final 2 x 48KB = 96KB
    const int SMEM_BIG = 131072;
    const int SMEM_FIN = 98304;
    cudaFuncSetAttribute(k_mma_ntrelu, cudaFuncAttributeMaxDynamicSharedMemorySize, SMEM_BIG);
    cudaFuncSetAttribute(k_u_mma,      cudaFuncAttributeMaxDynamicSharedMemorySize, SMEM_BIG);
    cudaFuncSetAttribute(k_final_mma,  cudaFuncAttributeMaxDynamicSharedMemorySize, SMEM_FIN);

    // 1) gather + splits + W1 transpose-split
    k_gather_split<<<BPD, 256>>>(span, preds);
    k_split4<<<(BSD * ND / 4 + 255) / 256, 256>>>(span, 0, BSD * ND / 4);
    k_split4<<<(ND * ND / 4 + 255) / 256, 256>>>(Wp, 1, ND * ND / 4);
    k_split4<<<(ND * ND / 4 + 255) / 256, 256>>>(Wa, 2, ND * ND / 4);
    k_w1t<<<dim3(32, 32, 64), dim3(32, 8)>>>(W1);

    // 2) unary scores (HMMA FFNN last layer + rowdot)
    k_mma_ntrelu<<<dim3(8, 4), 256, SMEM_BIG>>>(0, bpv);
    k_rowdot<<<BPD, 256>>>(wp, 0);
    k_mma_ntrelu<<<dim3(8, 32), 256, SMEM_BIG>>>(1, bav);
    k_rowdot<<<BSD, 256>>>(wa, 1);

    // 3) concat-linear terms
    k_gemm_nn64<<<dim3(1, BPD / 64), 256>>>(0, span, W2);
    k_gemm_nn64<<<dim3(1, BSD / 64), 256>>>(1, span, W2 + (size_t)ND * NL);

    // 4) bilinear stage 1 (HMMA pipelined, bf16 split, U -> bf16 hi/lo)
    k_u_mma<<<dim3(8, 4, 64), 256, SMEM_BIG>>>();

    // 5) bilinear stage 2 + full epilogue (HMMA pipelined)
    k_final_mma<<<dim3(4, 512), 256, SMEM_FIN>>>(bias, out);

    // 6) labels + tail
    const int n_scores = NB * NP * NS * NL;
    const int n_lab = NB * NP * NS;
    int written = n_scores;
    if (out_size >= n_scores + n_lab) {
        k_labels<<<(n_lab + 255) / 256, 256>>>(labels, out + n_scores, n_lab);
        written += n_lab;
    }
    if (out_size > written) {
        int rem = out_size - written;
        k_zero<<<(rem + 255) / 256, 256>>>(out + written, rem);
    }
}

// round 8
// speedup vs baseline: 3.6035x; 1.0907x over previous
#include <cuda_runtime.h>
#include <cuda_bf16.h>
#include <cstdint>

// Problem dims (fixed by reference)
#define NB 8
#define NP 64
#define NS 512
#define ND 1024
#define NL 64
#define BPD (NB * NP)   // 512
#define BSD (NB * NS)   // 4096

// ---------------- device scratch (static globals; no allocs allowed) ----------------
__device__ float g_pred[BPD * ND];
__device__ float g_hid[BSD * ND];     // span FFNN hidden
__device__ float g_hidp[BPD * ND];    // pred FFNN hidden
__device__ float g_psc[BPD];
__device__ float g_asc[BSD];
__device__ float g_p2[BPD * NL];
__device__ float g_s2[BSD * NL];
__device__ __nv_bfloat16 g_pred_h[BPD * ND], g_pred_l[BPD * ND];
__device__ __nv_bfloat16 g_span_h[BSD * ND], g_span_l[BSD * ND];
__device__ __nv_bfloat16 g_wp_h[ND * ND], g_wp_l[ND * ND];
__device__ __nv_bfloat16 g_wa_h[ND * ND], g_wa_l[ND * ND];
__device__ __nv_bfloat16 g_w1t_h[(size_t)NL * ND * ND], g_w1t_l[(size_t)NL * ND * ND]; // [l][e][d]
__device__ __nv_bfloat16 g_u_h[(size_t)BPD * NL * ND],  g_u_l[(size_t)BPD * NL * ND];  // [bp][l][e]

// ---------------- PTX helpers (plain sm_80+ features only) ----------------
__device__ __forceinline__ uint32_t smem_to_u32(const void* p) {
    uint32_t a;
    asm("{ .reg .u64 t; cvta.to.shared.u64 t, %1; cvt.u32.u64 %0, t; }" : "=r"(a) : "l"(p));
    return a;
}
__device__ __forceinline__ void ldm_x4(uint32_t* r, uint32_t a) {
    asm volatile("ldmatrix.sync.aligned.m8n8.x4.shared.b16 {%0,%1,%2,%3}, [%4];"
                 : "=r"(r[0]), "=r"(r[1]), "=r"(r[2]), "=r"(r[3]) : "r"(a));
}
__device__ __forceinline__ void mma_bf16(float* c, const uint32_t* a, const uint32_t* b) {
    asm volatile("mma.sync.aligned.m16n8k16.row.col.f32.bf16.bf16.f32 "
                 "{%0,%1,%2,%3}, {%4,%5,%6,%7}, {%8,%9}, {%0,%1,%2,%3};"
                 : "+f"(c[0]), "+f"(c[1]), "+f"(c[2]), "+f"(c[3])
                 : "r"(a[0]), "r"(a[1]), "r"(a[2]), "r"(a[3]), "r"(b[0]), "r"(b[1]));
}
__device__ __forceinline__ void cp16(uint32_t d, const void* s) {
    asm volatile("cp.async.cg.shared.global [%0], [%1], 16;" :: "r"(d), "l"(s));
}
#define CP_COMMIT() asm volatile("cp.async.commit_group;" ::: "memory")

// Stage layout (bytes from stage base): Ah @0 (16KB), Al @16K, Bh @32K, Bl @32K+BROWS*128
// Each tile row = 64 bf16 = 128B, SW128 swizzle o ^= (o>>3)&0x70.
template <int BROWS>
__device__ __forceinline__ void prefetch_chunk(
    uint32_t st, const __nv_bfloat16* Ah, const __nv_bfloat16* Al,
    const __nv_bfloat16* Bh, const __nv_bfloat16* Bl, int ch, int tid)
{
    const int co = ch * 64;
#pragma unroll
    for (int i = tid; i < 1024; i += 256) {
        int r = i >> 3, sg = i & 7;
        uint32_t o = (uint32_t)(r * 128 + sg * 16);
        o ^= (o >> 3) & 0x70;
        const size_t goff = (size_t)r * ND + co + sg * 8;
        cp16(st + o, Ah + goff);
        cp16(st + 16384 + o, Al + goff);
    }
#pragma unroll
    for (int i = tid; i < BROWS * 8; i += 256) {
        int r = i >> 3, sg = i & 7;
        uint32_t o = (uint32_t)(r * 128 + sg * 16);
        o ^= (o >> 3) & 0x70;
        const size_t goff = (size_t)r * ND + co + sg * 8;
        cp16(st + 32768 + o, Bh + goff);
        cp16(st + 32768 + BROWS * 128 + o, Bl + goff);
    }
}

// Per-chunk MMA: all frags loaded once per kk, then 3 product passes
// (product-major order keeps dependent MMAs on one accumulator 16 instrs apart)
// C += Ah*Bh + Ah*Bl + Al*Bh
template <int MF, int NF, int BROWS>
__device__ __forceinline__ void mma_chunk(float (&acc)[MF][NF][4], uint32_t st,
                                          int lane, int warpM, int warpN)
{
#pragma unroll
    for (int kk = 0; kk < 4; kk++) {
        uint32_t afH[MF][4], afL[MF][4];
#pragma unroll
        for (int mf = 0; mf < MF; mf++) {
            uint32_t row = warpM + mf * 16 + (lane & 15);
            uint32_t kb = kk * 16 + ((lane >> 4) << 3);
            uint32_t o = row * 128 + kb * 2;
            o ^= (o >> 3) & 0x70;
            ldm_x4(afH[mf], st + o);
            ldm_x4(afL[mf], st + 16384 + o);
        }
        uint32_t bfH[NF][2], bfL[NF][2];
#pragma unroll
        for (int nb = 0; nb < NF / 2; nb++) {
            uint32_t row = warpN + nb * 16 + (lane & 7) + ((lane >> 4) & 1) * 8;
            uint32_t kb = kk * 16 + ((lane >> 3) & 1) * 8;
            uint32_t o = row * 128 + kb * 2;
            o ^= (o >> 3) & 0x70;
            uint32_t t[4];
            ldm_x4(t, st + 32768 + o);
            bfH[2 * nb][0] = t[0]; bfH[2 * nb][1] = t[1];
            bfH[2 * nb + 1][0] = t[2]; bfH[2 * nb + 1][1] = t[3];
            ldm_x4(t, st + 32768 + BROWS * 128 + o);
            bfL[2 * nb][0] = t[0]; bfL[2 * nb][1] = t[1];
            bfL[2 * nb + 1][0] = t[2]; bfL[2 * nb + 1][1] = t[3];
        }
        // pass 1: Ah*Bh
#pragma unroll
        for (int mf = 0; mf < MF; mf++)
#pragma unroll
            for (int nf = 0; nf < NF; nf++)
                mma_bf16(acc[mf][nf], afH[mf], bfH[nf]);
        // pass 2: Ah*Bl
#pragma unroll
        for (int mf = 0; mf < MF; mf++)
#pragma unroll
            for (int nf = 0; nf < NF; nf++)
                mma_bf16(acc[mf][nf], afH[mf], bfL[nf]);
        // pass 3: Al*Bh
#pragma unroll
        for (int mf = 0; mf < MF; mf++)
#pragma unroll
            for (int nf = 0; nf < NF; nf++)
                mma_bf16(acc[mf][nf], afL[mf], bfH[nf]);
    }
}

// Pipeline over 16 K-chunks of 64, STAGES-deep, ONE __syncthreads per chunk.
// Layout per chunk: wait(S-2) -> sync -> prefetch(ch+S-1) -> mma(ch)
//  - sync after wait: all threads' cp.async groups for chunk ch complete before reads
//  - prefetch after sync: all threads done with mma(ch-1), whose buffer is reused
template <int MF, int NF, int BROWS, int STAGES>
__device__ __forceinline__ void gemm_pipe(
    float (&acc)[MF][NF][4],
    const __nv_bfloat16* Ah, const __nv_bfloat16* Al,
    const __nv_bfloat16* Bh, const __nv_bfloat16* Bl,
    uint32_t sm, int tid, int lane, int warpM, int warpN)
{
    const uint32_t STAGE = 32768u + 2u * BROWS * 128u;
#pragma unroll
    for (int s = 0; s < STAGES - 1; s++) {
        prefetch_chunk<BROWS>(sm + s * STAGE, Ah, Al, Bh, Bl, s, tid);
        CP_COMMIT();
    }
#pragma unroll 1
    for (int ch = 0; ch < 16; ch++) {
        asm volatile("cp.async.wait_group %0;" :: "n"(STAGES - 2));
        __syncthreads();
        int nx = ch + STAGES - 1;
        if (nx < 16)
            prefetch_chunk<BROWS>(sm + (uint32_t)(nx % STAGES) * STAGE, Ah, Al, Bh, Bl, nx, tid);
        CP_COMMIT();
        mma_chunk<MF, NF, BROWS>(acc, sm + (uint32_t)(ch % STAGES) * STAGE, lane, warpM, warpN);
    }
}

// ---------------- FFNN last layer (merged pred+span): hid = relu(A @ W^T + bias) ----------------
// blockIdx.y < 4: pred rows -> g_hidp (weights Wp); else span rows -> g_hid (weights Wa)
__global__ __launch_bounds__(256, 1) void k_mma_ntrelu(const float* __restrict__ bpv,
                                                       const float* __restrict__ bav)
{
    extern __shared__ __align__(1024) char dsm[];
    const uint32_t sm = smem_to_u32(dsm);
    const int tid = threadIdx.x, lane = tid & 31, wid = tid >> 5;
    const int warpM = (wid >> 2) * 64, warpN = (wid & 3) * 32;
    const int isSpan = blockIdx.y >= 4;
    const int mBase = (isSpan ? (blockIdx.y - 4) : blockIdx.y) * 128;
    const int nBase = blockIdx.x * 128;
    const float* bias = isSpan ? bav : bpv;

    const __nv_bfloat16* Ah = (isSpan ? g_span_h : g_pred_h) + (size_t)mBase * ND;
    const __nv_bfloat16* Al = (isSpan ? g_span_l : g_pred_l) + (size_t)mBase * ND;
    const __nv_bfloat16* Wh = (isSpan ? g_wa_h : g_wp_h) + (size_t)nBase * ND;
    const __nv_bfloat16* Wl = (isSpan ? g_wa_l : g_wp_l) + (size_t)nBase * ND;
    float* hid = isSpan ? g_hid : g_hidp;

    float acc[4][4][4] = {};
    gemm_pipe<4, 4, 128, 3>(acc, Ah, Al, Wh, Wl, sm, tid, lane, warpM, warpN);

#pragma unroll
    for (int mf = 0; mf < 4; mf++)
#pragma unroll
        for (int h = 0; h < 2; h++) {
            int row = mBase + warpM + mf * 16 + (lane >> 2) + h * 8;
            float* orow = hid + (size_t)row * ND;
#pragma unroll
            for (int nf = 0; nf < 4; nf++) {
                int col = nBase + warpN + nf * 8 + (lane & 3) * 2;
                float2 v;
                v.x = fmaxf(acc[mf][nf][2 * h + 0] + bias[col], 0.f);
                v.y = fmaxf(acc[mf][nf][2 * h + 1] + bias[col + 1], 0.f);
                *(float2*)(orow + col) = v;
            }
        }
}

// ---------------- Stage 1: U[bp, l, e] = pred[bp,:] . W1t[l, e, :]; write bf16 hi/lo ----------------
__global__ __launch_bounds__(256, 1) void k_u_mma()
{
    extern __shared__ __align__(1024) char dsm[];
    const uint32_t sm = smem_to_u32(dsm);
    const int tid = threadIdx.x, lane = tid & 31, wid = tid >> 5;
    const int warpM = (wid >> 2) * 64, warpN = (wid & 3) * 32;
    const int nBase = blockIdx.x * 128, mBase = blockIdx.y * 128, l = blockIdx.z;

    const __nv_bfloat16* Ah = g_pred_h + (size_t)mBase * ND;
    const __nv_bfloat16* Al = g_pred_l + (size_t)mBase * ND;
    const __nv_bfloat16* Bh = g_w1t_h + ((size_t)l * ND + nBase) * ND;
    const __nv_bfloat16* Bl = g_w1t_l + ((size_t)l * ND + nBase) * ND;

    float acc[4][4][4] = {};
    gemm_pipe<4, 4, 128, 3>(acc, Ah, Al, Bh, Bl, sm, tid, lane, warpM, warpN);

#pragma unroll
    for (int mf = 0; mf < 4; mf++)
#pragma unroll
        for (int h = 0; h < 2; h++) {
            int row = mBase + warpM + mf * 16 + (lane >> 2) + h * 8;
            size_t base = ((size_t)row * NL + l) * ND;
#pragma unroll
            for (int nf = 0; nf < 4; nf++) {
                int col = nBase + warpN + nf * 8 + (lane & 3) * 2;
                float v0 = acc[mf][nf][2 * h + 0], v1 = acc[mf][nf][2 * h + 1];
                __nv_bfloat16 h0 = __float2bfloat16(v0), h1 = __float2bfloat16(v1);
                __nv_bfloat16 q0 = __float2bfloat16(v0 - __bfloat162float(h0));
                __nv_bfloat16 q1 = __float2bfloat16(v1 - __bfloat162float(h1));
                *(__nv_bfloat162*)(g_u_h + base + col) = __halves2bfloat162(h0, h1);
                *(__nv_bfloat162*)(g_u_l + base + col) = __halves2bfloat162(q0, q1);
            }
        }
}

// ---------------- Stage 2 + full epilogue -> scores ----------------
__global__ __launch_bounds__(256, 2) void k_final_mma(const float* __restrict__ bias,
                                                      float* __restrict__ out)
{
    extern __shared__ __align__(1024) char dsm[];
    const uint32_t sm = smem_to_u32(dsm);
    const int tid = threadIdx.x, lane = tid & 31, wid = tid >> 5;
    const int warpM = (wid >> 1) * 32, warpN = (wid & 1) * 32;
    const int mBase = blockIdx.x * 128, bp = blockIdx.y, b = bp >> 6;

    const __nv_bfloat16* Ah = g_span_h + ((size_t)b * NS + mBase) * ND;
    const __nv_bfloat16* Al = g_span_l + ((size_t)b * NS + mBase) * ND;
    const __nv_bfloat16* Bh = g_u_h + (size_t)bp * NL * ND;
    const __nv_bfloat16* Bl = g_u_l + (size_t)bp * NL * ND;

    float acc[2][4][4] = {};
    gemm_pipe<2, 4, 64, 2>(acc, Ah, Al, Bh, Bl, sm, tid, lane, warpM, warpN);

    const float* p2 = g_p2 + (size_t)bp * NL;
#pragma unroll
    for (int mf = 0; mf < 2; mf++)
#pragma unroll
        for (int h = 0; h < 2; h++) {
            int s = mBase + warpM + mf * 16 + (lane >> 2) + h * 8;
            size_t srow = (size_t)b * NS + s;
            float add = g_psc[bp] + g_asc[srow];
            const float* s2 = g_s2 + srow * NL;
            float* orow = out + ((size_t)bp * NS + s) * NL;
#pragma unroll
            for (int nf = 0; nf < 4; nf++) {
                int col = warpN + nf * 8 + (lane & 3) * 2;
                float2 v;
                v.x = acc[mf][nf][2 * h + 0] + p2[col] + s2[col] + bias[col] + add;
                v.y = acc[mf][nf][2 * h + 1] + p2[col + 1] + s2[col + 1] + bias[col + 1] + add;
                if (col + 1 == NL - 1) v.y = 0.f;   // null-label column
                *(float2*)(orow + col) = v;
            }
        }
}

// ---------------- gather predicate rows + bf16 split ----------------
__global__ __launch_bounds__(256) void k_gather_split(const float* __restrict__ span,
                                                      const int* __restrict__ preds) {
    int bp = blockIdx.x;
    int b = bp / NP;
    int s = preds[bp];
    float4 v = ((const float4*)(span + ((size_t)b * NS + s) * ND))[threadIdx.x];
    ((float4*)(g_pred + (size_t)bp * ND))[threadIdx.x] = v;
    __nv_bfloat16 h0 = __float2bfloat16(v.x), h1 = __float2bfloat16(v.y);
    __nv_bfloat16 h2 = __float2bfloat16(v.z), h3 = __float2bfloat16(v.w);
    __nv_bfloat162* ph = (__nv_bfloat162*)(g_pred_h + (size_t)bp * ND);
    __nv_bfloat162* pl = (__nv_bfloat162*)(g_pred_l + (size_t)bp * ND);
    ph[threadIdx.x * 2 + 0] = __halves2bfloat162(h0, h1);
    ph[threadIdx.x * 2 + 1] = __halves2bfloat162(h2, h3);
    pl[threadIdx.x * 2 + 0] = __halves2bfloat162(__float2bfloat16(v.x - __bfloat162float(h0)),
                                                 __float2bfloat16(v.y - __bfloat162float(h1)));
    pl[threadIdx.x * 2 + 1] = __halves2bfloat162(__float2bfloat16(v.z - __bfloat162float(h2)),
                                                 __float2bfloat16(v.w - __bfloat162float(h3)));
}

// ---------------- generic fp32 -> (hi, lo) bf16 split: 0->span, 1->Wp, 2->Wa ----------------
__global__ __launch_bounds__(256) void k_split4(const float* __restrict__ x, int which, int n4) {
    int i = blockIdx.x * 256 + threadIdx.x;
    if (i >= n4) return;
    __nv_bfloat16* H = which == 0 ? g_span_h : (which == 1 ? g_wp_h : g_wa_h);
    __nv_bfloat16* L = which == 0 ? g_span_l : (which == 1 ? g_wp_l : g_wa_l);
    float4 v = ((const float4*)x)[i];
    __nv_bfloat16 h0 = __float2bfloat16(v.x), h1 = __float2bfloat16(v.y);
    __nv_bfloat16 h2 = __float2bfloat16(v.z), h3 = __float2bfloat16(v.w);
    ((__nv_bfloat162*)H)[2 * i + 0] = __halves2bfloat162(h0, h1);
    ((__nv_bfloat162*)H)[2 * i + 1] = __halves2bfloat162(h2, h3);
    ((__nv_bfloat162*)L)[2 * i + 0] = __halves2bfloat162(__float2bfloat16(v.x - __bfloat162float(h0)),
                                                         __float2bfloat16(v.y - __bfloat162float(h1)));
    ((__nv_bfloat162*)L)[2 * i + 1] = __halves2bfloat162(__float2bfloat16(v.z - __bfloat162float(h2)),
                                                         __float2bfloat16(v.w - __bfloat162float(h3)));
}

// ---------------- W1 transpose + split: W1t[l][e][d] = split(W1[l][d][e]) ----------------
__global__ __launch_bounds__(256) void k_w1t(const float* __restrict__ W1) {
    __shared__ float t[32][33];
    const int l = blockIdx.z;
    const int e0 = blockIdx.x * 32, d0 = blockIdx.y * 32;
    const int tx = threadIdx.x, ty = threadIdx.y;   // (32, 8)
    const float* src = W1 + (size_t)l * ND * ND;
#pragma unroll
    for (int i = ty; i < 32; i += 8)
        t[i][tx] = src[(size_t)(d0 + i) * ND + e0 + tx];
    __syncthreads();
    const size_t dbase = (size_t)l * ND * ND;
#pragma unroll
    for (int i = ty; i < 32; i += 8) {
        float v = t[tx][i];                         // = W1[l][d0+tx][e0+i]
        __nv_bfloat16 h = __float2bfloat16(v);
        g_w1t_h[dbase + (size_t)(e0 + i) * ND + d0 + tx] = h;
        g_w1t_l[dbase + (size_t)(e0 + i) * ND + d0 + tx] =
            __float2bfloat16(v - __bfloat162float(h));
    }
}

// ---------------- merged row dot: blocks [0,4096) -> asc (wa, g_hid); [4096,4608) -> psc ----------------
__global__ __launch_bounds__(256) void k_rowdot(const float* __restrict__ wp,
                                                const float* __restrict__ wa) {
    int r = blockIdx.x;
    const int isPred = r >= BSD;
    const float* Hp = isPred ? (g_hidp + (size_t)(r - BSD) * ND) : (g_hid + (size_t)r * ND);
    const float* w = isPred ? wp : wa;
    float s = 0.f;
    for (int j = threadIdx.x; j < ND; j += 256) s = fmaf(Hp[j], w[j], s);
    __shared__ float red[256];
    red[threadIdx.x] = s;
    __syncthreads();
    for (int o = 128; o > 0; o >>= 1) {
        if (threadIdx.x < o) red[threadIdx.x] += red[threadIdx.x + o];
        __syncthreads();
    }
    if (threadIdx.x == 0) {
        if (isPred) g_psc[r - BSD] = red[0];
        else        g_asc[r] = red[0];
    }
}

// ---------------- merged NN GEMM M x 64, K=1024: y<8 -> pred/p2, else span/s2 ----------------
__global__ __launch_bounds__(256) void k_gemm_nn64(const float* __restrict__ span,
                                                   const float* __restrict__ W2) {
    const int isSpan = blockIdx.y >= 8;
    const float* A = isSpan ? span : g_pred;
    const float* Bw = W2 + (isSpan ? (size_t)ND * NL : 0);
    float* C = isSpan ? g_s2 : g_p2;
    const int rowBase = (isSpan ? (blockIdx.y - 8) : blockIdx.y) * 64;

    __shared__ float As[16][64];
    __shared__ float Bs[16][64];
    const int tid = threadIdx.x;
    const int tx = tid & 15, ty = tid >> 4;
    const int alr = tid >> 2;
    const int alc = (tid & 3) << 2;
    const float* Ap = A + (size_t)(rowBase + alr) * ND + alc;
    const int blr = tid >> 4;
    const int blc = (tid & 15) << 2;
    const float* Bp = Bw + (size_t)blr * NL + blc;

    float acc[4][4];
#pragma unroll
    for (int i = 0; i < 4; i++)
#pragma unroll
        for (int j = 0; j < 4; j++) acc[i][j] = 0.f;

    for (int k0 = 0; k0 < ND; k0 += 16) {
        float4 av = *(const float4*)(Ap + k0);
        As[alc + 0][alr] = av.x;
        As[alc + 1][alr] = av.y;
        As[alc + 2][alr] = av.z;
        As[alc + 3][alr] = av.w;
        float4 bv = *(const float4*)(Bp + (size_t)k0 * NL);
        *(float4*)&Bs[blr][blc] = bv;
        __syncthreads();
#pragma unroll
        for (int k = 0; k < 16; k++) {
            float4 a4 = *(const float4*)&As[k][ty * 4];
            float4 b4 = *(const float4*)&Bs[k][tx * 4];
            float a[4] = {a4.x, a4.y, a4.z, a4.w};
            float bb[4] = {b4.x, b4.y, b4.z, b4.w};
#pragma unroll
            for (int i = 0; i < 4; i++)
#pragma unroll
                for (int j = 0; j < 4; j++)
                    acc[i][j] = fmaf(a[i], bb[j], acc[i][j]);
        }
        __syncthreads();
    }
#pragma unroll
    for (int i = 0; i < 4; i++) {
        int row = rowBase + ty * 4 + i;
        *(float4*)(C + (size_t)row * NL + tx * 4) =
            make_float4(acc[i][0], acc[i][1], acc[i][2], acc[i][3]);
    }
}

// ---------------- labels cast + tail zero ----------------
__global__ void k_labels(const int* __restrict__ lab, float* __restrict__ out, int n) {
    int i = blockIdx.x * blockDim.x + threadIdx.x;
    if (i < n) out[i] = (float)lab[i];
}
__global__ void k_zero(float* __restrict__ out, int n) {
    int i = blockIdx.x * blockDim.x + threadIdx.x;
    if (i < n) out[i] = 0.f;
}

// ---------------- host ----------------
extern "C" void kernel_launch(void* const* d_in, const int* in_sizes, int n_in,
                              void* d_out, int out_size)
{
    const float* span   = (const float*)d_in[0];
    const int*   preds  = (const int*)d_in[1];
    const int*   labels = (const int*)d_in[2];
    // d_in[3] = len_info (dense, unused)
    // FFNN bug: only the LAST layer (index 1) of each stack matters.
    const float* Wp   = (const float*)d_in[4] + (size_t)ND * ND;
    const float* bpv  = (const float*)d_in[5] + ND;
    const float* Wa   = (const float*)d_in[6] + (size_t)ND * ND;
    const float* bav  = (const float*)d_in[7] + ND;
    const float* wp   = (const float*)d_in[8];
    const float* wa   = (const float*)d_in[9];
    const float* W1   = (const float*)d_in[10];
    const float* W2   = (const float*)d_in[11];
    const float* bias = (const float*)d_in[12];
    float* out = (float*)d_out;

    // dynamic smem: big kernels 3 stages x 64KB = 192KB; final 2 x 48KB = 96KB (2 CTAs/SM)
    const int SMEM_BIG = 196608;
    const int SMEM_FIN = 98304;
    cudaFuncSetAttribute(k_mma_ntrelu, cudaFuncAttributeMaxDynamicSharedMemorySize, SMEM_BIG);
    cudaFuncSetAttribute(k_u_mma,      cudaFuncAttributeMaxDynamicSharedMemorySize, SMEM_BIG);
    cudaFuncSetAttribute(k_final_mma,  cudaFuncAttributeMaxDynamicSharedMemorySize, SMEM_FIN);

    // 1) gather + splits + W1 transpose-split
    k_gather_split<<<BPD, 256>>>(span, preds);
    k_split4<<<(BSD * ND / 4 + 255) / 256, 256>>>(span, 0, BSD * ND / 4);
    k_split4<<<(ND * ND / 4 + 255) / 256, 256>>>(Wp, 1, ND * ND / 4);
    k_split4<<<(ND * ND / 4 + 255) / 256, 256>>>(Wa, 2, ND * ND / 4);
    k_w1t<<<dim3(32, 32, 64), dim3(32, 8)>>>(W1);

    // 2) unary path: one merged FFNN launch (pred tiles y<4, span tiles y>=4), one rowdot
    k_mma_ntrelu<<<dim3(8, 36), 256, SMEM_BIG>>>(bpv, bav);
    k_rowdot<<<BSD + BPD, 256>>>(wp, wa);

    // 3) concat-linear terms (merged)
    k_gemm_nn64<<<dim3(1, 72), 256>>>(span, W2);

    // 4) bilinear stage 1 (HMMA 3-stage pipeline, bf16 split, U -> bf16 hi/lo)
    k_u_mma<<<dim3(8, 4, 64), 256, SMEM_BIG>>>();

    // 5) bilinear stage 2 + full epilogue (HMMA 2-stage, 2 CTAs/SM)
    k_final_mma<<<dim3(4, 512), 256, SMEM_FIN>>>(bias, out);

    // 6) labels + tail
    const int n_scores = NB * NP * NS * NL;
    const int n_lab = NB * NP * NS;
    int written = n_scores;
    if (out_size >= n_scores + n_lab) {
        k_labels<<<(n_lab + 255) / 256, 256>>>(labels, out + n_scores, n_lab);
        written += n_lab;
    }
    if (out_size > written) {
        int rem = out_size - written;
        k_zero<<<(rem + 255) / 256, 256>>>(out + written, rem);
    }
}